// round 7
// baseline (speedup 1.0000x reference)
#include <cuda_runtime.h>
#include <cuda_bf16.h>
#include <cstdint>

// Problem dims
#define N_  32
#define C_  64
#define T_  128
#define V_  25
#define F_  204800      // C*T*V
#define H_  256
#define E_  4

// Split-K config for GEMM0
#define S_SPLIT 512
#define FC      400     // F_/S_SPLIT
#define KT      16      // f-tile staged in smem
#define NTILES  (FC / KT)   // 25

// k1 dynamic smem layout (floats): 3 W buffers + 3 x buffers
#define K1_WBUF   (KT * H_)          // 4096 floats
#define K1_XBUF   (KT * 32)          // 512 floats
#define K1_SMEMF  (3 * K1_WBUF + 3 * K1_XBUF)
#define K1_SMEMB  (K1_SMEMF * 4)     // 55296 B

// k3 dims
#define K3_T      8                  // t per block
#define K3_XPAD   26
#define K3_APAD   26
#define K3_XSZ    (K3_T * C_ * K3_XPAD)    // 13312 floats
#define K3_ASZ    (K3_T * V_ * K3_APAD)    // 5200 floats
#define K3_SMEMF  (K3_XSZ + K3_ASZ + 4)
#define K3_SMEMB  (K3_SMEMF * 4)           // 74064 B

// Scratch (static device globals — no allocation)
__device__ float g_partials[S_SPLIT * N_ * H_];   // 16.7 MB
__device__ float g_h0[N_ * H_];
__device__ float g_wgt[N_ * E_];

// ---------------- f32x2 helpers (sm_103a packed fp32 FMA) ----------------
static __device__ __forceinline__ unsigned long long pack2(float lo, float hi) {
    unsigned long long r;
    asm("mov.b64 %0, {%1, %2};" : "=l"(r) : "f"(lo), "f"(hi));
    return r;
}
static __device__ __forceinline__ void unpack2(unsigned long long p, float& lo, float& hi) {
    asm("mov.b64 {%0, %1}, %2;" : "=f"(lo), "=f"(hi) : "l"(p));
}
static __device__ __forceinline__ void ffma2(unsigned long long& acc,
                                             unsigned long long a,
                                             unsigned long long b) {
    asm("fma.rn.f32x2 %0, %1, %2, %0;" : "+l"(acc) : "l"(a), "l"(b));
}

static __device__ __forceinline__ void cp_async16(unsigned int smem_addr, const void* gptr) {
    asm volatile("cp.async.cg.shared.global [%0], [%1], 16;"
                 :: "r"(smem_addr), "l"(gptr));
}
static __device__ __forceinline__ void cp_commit() {
    asm volatile("cp.async.commit_group;");
}
template <int NN>
static __device__ __forceinline__ void cp_wait() {
    asm volatile("cp.async.wait_group %0;" :: "n"(NN));
}

// ---------------- Kernel 1: split-K GEMM0 (3-stage cp.async pipeline) ------
// Grid: S_SPLIT blocks, 128 threads. Thread tile: 16 n (8 f32x2 pairs) x 4 h.
__global__ __launch_bounds__(128, 4)
void k1_gemm0(const float* __restrict__ x, const float* __restrict__ W0) {
    extern __shared__ __align__(16) float sm1[];
    float* wbuf = sm1;                       // 3 * KT*H_
    float* xbuf = sm1 + 3 * K1_WBUF;         // 3 * KT*32

    const int tid = threadIdx.x;
    const int pg  = tid >> 6;            // 0..1  -> n-pair group
    const int hg  = tid & 63;            // 0..63 -> h group
    const int h0  = hg << 2;             // 4 h per thread
    const int fbase = blockIdx.x * FC;

    const int ln = tid >> 2;             // 0..31 : n row for x staging
    const int lj = tid & 3;              // 0..3  : f quad

    unsigned long long acc[8][4];
#pragma unroll
    for (int i = 0; i < 8; i++)
#pragma unroll
        for (int j = 0; j < 4; j++) acc[i][j] = 0ull;

    // stage W tile -> buffer (one commit group)
    auto stage_w = [&](int tile, int buf) {
        const int f0 = fbase + tile * KT;
        float* dst = wbuf + buf * K1_WBUF;
#pragma unroll
        for (int k = 0; k < 8; k++) {
            const int cid = tid + 128 * k;     // 0..1023
            const int r   = cid >> 6;          // row 0..15
            const int c16 = cid & 63;          // 16B chunk in row
            unsigned int sa = (unsigned int)__cvta_generic_to_shared(
                                  dst + r * H_ + c16 * 4);
            cp_async16(sa, W0 + (size_t)(f0 + r) * H_ + c16 * 4);
        }
        cp_commit();
    };
    auto stage_x = [&](int tile, int buf, const float4& xv) {
        float* xd = xbuf + buf * K1_XBUF;
        xd[(lj * 4 + 0) * 32 + ln] = xv.x;
        xd[(lj * 4 + 1) * 32 + ln] = xv.y;
        xd[(lj * 4 + 2) * 32 + ln] = xv.z;
        xd[(lj * 4 + 3) * 32 + ln] = xv.w;
    };

    // ---- prologue: tiles 0 and 1 ----
    stage_w(0, 0);
    stage_w(1, 1);
    {
        const float4 x0 = *(const float4*)(x + (size_t)ln * F_ + fbase + 0 * KT + lj * 4);
        const float4 x1 = *(const float4*)(x + (size_t)ln * F_ + fbase + 1 * KT + lj * 4);
        stage_x(0, 0, x0);
        stage_x(1, 1, x1);
    }

    for (int t = 0; t < NTILES; t++) {
        if (t == NTILES - 1) cp_wait<0>(); else cp_wait<1>();
        __syncthreads();                 // tile t data visible to all

        const int cb = t % 3;
        const bool pre = (t + 2 < NTILES);
        float4 xv;
        if (pre) {
            stage_w(t + 2, (t + 2) % 3);
            xv = *(const float4*)(x + (size_t)ln * F_ + fbase + (t + 2) * KT + lj * 4);
        }

        // ---- compute tile t from smem ----
        const float* wb = wbuf + cb * K1_WBUF;
        const float* xb = xbuf + cb * K1_XBUF;
#pragma unroll
        for (int fl = 0; fl < KT; fl++) {
            const float4 w4 = *(const float4*)(wb + fl * H_ + h0);
            unsigned long long w2[4];
            w2[0] = pack2(w4.x, w4.x);
            w2[1] = pack2(w4.y, w4.y);
            w2[2] = pack2(w4.z, w4.z);
            w2[3] = pack2(w4.w, w4.w);

            const ulonglong2* xr = (const ulonglong2*)(xb + fl * 32 + pg * 16);
            const ulonglong2 q0 = xr[0], q1 = xr[1], q2 = xr[2], q3 = xr[3];
            const unsigned long long xp[8] = {q0.x, q0.y, q1.x, q1.y,
                                              q2.x, q2.y, q3.x, q3.y};
#pragma unroll
            for (int i = 0; i < 8; i++)
#pragma unroll
                for (int j = 0; j < 4; j++)
                    ffma2(acc[i][j], xp[i], w2[j]);
        }

        if (pre) stage_x(t + 2, (t + 2) % 3, xv);
    }

    // Write deterministic partials
    float* outp = g_partials + (size_t)blockIdx.x * (N_ * H_);
#pragma unroll
    for (int i = 0; i < 8; i++) {
        const int n = (pg * 8 + i) * 2;
#pragma unroll
        for (int j = 0; j < 4; j++) {
            float lo, hi;
            unpack2(acc[i][j], lo, hi);
            outp[(n + 0) * H_ + h0 + j] = lo;
            outp[(n + 1) * H_ + h0 + j] = hi;
        }
    }
}

// ---------------- Kernel 2a: parallel split-K reduce + bias + ELU ----------
// Grid: 256 blocks = (32 n) x (8 h-groups); 256 threads = 32 h x 8 q-chunks.
__global__ __launch_bounds__(256)
void k2a_reduce(const float* __restrict__ b0) {
    __shared__ float red[8][33];

    const int n  = blockIdx.x >> 3;
    const int hq = blockIdx.x & 7;
    const int hl = threadIdx.x & 31;
    const int rg = threadIdx.x >> 5;     // 0..7
    const int h  = hq * 32 + hl;

    float s = 0.f;
    const float* p = g_partials + (size_t)n * H_ + h;
#pragma unroll 8
    for (int q = rg; q < S_SPLIT; q += 8)
        s += p[(size_t)q * (N_ * H_)];

    red[rg][hl] = s;
    __syncthreads();

    if (rg == 0) {
        float v = red[0][hl];
#pragma unroll
        for (int r = 1; r < 8; r++) v += red[r][hl];
        v += b0[h];
        v = (v > 0.f) ? v : expm1f(v);   // ELU
        g_h0[n * H_ + h] = v;
    }
}

// ---------------- Kernel 2b: MLP layers 2/3 + softmax -> g_wgt -------------
// Grid: 32 blocks (one per n), 256 threads (one per h).
__global__ __launch_bounds__(H_)
void k2b_mlp(const float* __restrict__ W1, const float* __restrict__ b1,
             const float* __restrict__ W2, const float* __restrict__ b2) {
    __shared__ float sh0[H_];
    __shared__ float sh1[H_];
    __shared__ float lg[E_];

    const int n = blockIdx.x;
    const int h = threadIdx.x;

    sh0[h] = g_h0[n * H_ + h];
    __syncthreads();

    float a = 0.f;
#pragma unroll 8
    for (int k = 0; k < H_; k++) a += sh0[k] * W1[k * H_ + h];
    a += b1[h];
    a = (a > 0.f) ? a : expm1f(a);
    sh1[h] = a;
    __syncthreads();

    if (h < E_) {
        float l = 0.f;
#pragma unroll 8
        for (int k = 0; k < H_; k++) l += sh1[k] * W2[k * E_ + h];
        lg[h] = l + b2[h];
    }
    __syncthreads();

    if (h == 0) {
        const float m = fmaxf(fmaxf(lg[0], lg[1]), fmaxf(lg[2], lg[3]));
        float e[E_];
        float den = 0.f;
#pragma unroll
        for (int ee = 0; ee < E_; ee++) { e[ee] = expf(lg[ee] - m); den += e[ee]; }
        const float inv = 1.f / den;
#pragma unroll
        for (int ee = 0; ee < E_; ee++) g_wgt[n * E_ + ee] = e[ee] * inv;
    }
}

// ---------------- Kernel 3: AS mix + batched graph conv --------------------
// Grid: 32 n x 16 t-octets = 512 blocks, 256 threads (8 warps).
// Warp w handles t = t0 + w; lane owns c-rows {lane, lane+32} -> 2 rows/thread.
__global__ __launch_bounds__(256, 3)
void k3_out(const float* __restrict__ x, const float* __restrict__ A,
            float* __restrict__ out) {
    extern __shared__ __align__(16) float sm3[];
    float* x_sh  = sm3;                      // [t][c][26]
    float* AS_sh = sm3 + K3_XSZ;             // [t][v][26]
    float* wn    = sm3 + K3_XSZ + K3_ASZ;    // 4

    const int tid = threadIdx.x;
    const int n   = blockIdx.x >> 4;
    const int tq  = blockIdx.x & 15;
    const int t0  = tq * K3_T;

    if (tid < E_) wn[tid] = g_wgt[n * E_ + tid];
    __syncthreads();

    // AS[t][v][w] = sum_e wn[e] * A[e][t0+t][v][w]
    for (int idx = tid; idx < K3_T * V_ * V_; idx += 256) {
        const int tt = idx / (V_ * V_);
        const int r  = idx - tt * (V_ * V_);
        const int v  = r / V_;
        const int w  = r - v * V_;
        const float* Ab = A + (size_t)(t0 + tt) * (V_ * V_) + r;
        AS_sh[tt * (V_ * K3_APAD) + v * K3_APAD + w] =
              wn[0] * Ab[0]
            + wn[1] * Ab[1 * T_ * V_ * V_]
            + wn[2] * Ab[2 * T_ * V_ * V_]
            + wn[3] * Ab[3 * T_ * V_ * V_];
    }

    // Stage x[n, :, t0:t0+8, :] — 200 contiguous floats per c (8t x 25v)
    for (int q = tid; q < C_ * 50; q += 256) {           // 3200 float4
        const int c = q / 50;
        const int r = q - c * 50;
        const float4 xv = *(const float4*)(x + (size_t)n * F_ + c * (T_ * V_)
                                             + t0 * V_ + r * 4);
        const int m0 = r * 4;
#pragma unroll
        for (int s = 0; s < 4; s++) {
            const int m  = m0 + s;
            const int tt = m / 25;
            const int v  = m - tt * 25;
            const float val = (s == 0) ? xv.x : (s == 1) ? xv.y : (s == 2) ? xv.z : xv.w;
            x_sh[tt * (C_ * K3_XPAD) + c * K3_XPAD + v] = val;
        }
    }
    __syncthreads();

    const int w    = tid >> 5;           // warp -> local t (uniform per warp)
    const int lane = tid & 31;

    const float* xr0 = x_sh + w * (C_ * K3_XPAD) + lane * K3_XPAD;
    const float* xr1 = xr0 + 32 * K3_XPAD;
    const float* asb = AS_sh + w * (V_ * K3_APAD);

    unsigned long long a0[12], a1[12];
#pragma unroll
    for (int j = 0; j < 12; j++) { a0[j] = 0ull; a1[j] = 0ull; }
    float s0 = 0.f, s1 = 0.f;

#pragma unroll
    for (int v = 0; v < V_; v++) {
        const float xv0 = xr0[v];
        const float xv1 = xr1[v];
        const unsigned long long p0 = pack2(xv0, xv0);
        const unsigned long long p1 = pack2(xv1, xv1);
        const unsigned long long* row =
            (const unsigned long long*)(asb + v * K3_APAD);
        const float last = ((const float*)row)[24];
#pragma unroll
        for (int j = 0; j < 12; j++) {
            ffma2(a0[j], p0, row[j]);
            ffma2(a1[j], p1, row[j]);
        }
        s0 += xv0 * last;
        s1 += xv1 * last;
    }

    __syncthreads();   // done reading x_sh — reuse as out staging [c][200]

    float* osh = x_sh;
    float* o0 = osh + lane * 200 + w * 25;
    float* o1 = osh + (lane + 32) * 200 + w * 25;
#pragma unroll
    for (int j = 0; j < 12; j++) {
        float lo, hi;
        unpack2(a0[j], lo, hi);
        o0[2 * j + 0] = lo; o0[2 * j + 1] = hi;
        unpack2(a1[j], lo, hi);
        o1[2 * j + 0] = lo; o1[2 * j + 1] = hi;
    }
    o0[24] = s0;
    o1[24] = s1;
    __syncthreads();

    // Coalesced float4 copy-out: per c, 200 contiguous floats in gmem
    for (int q = tid; q < C_ * 50; q += 256) {
        const int c = q / 50;
        const int r = q - c * 50;
        const float4 v4 = *(const float4*)(osh + c * 200 + r * 4);
        *(float4*)(out + (size_t)n * F_ + c * (T_ * V_) + t0 * V_ + r * 4) = v4;
    }
}

// ---------------- launch ----------------
extern "C" void kernel_launch(void* const* d_in, const int* in_sizes, int n_in,
                              void* d_out, int out_size) {
    (void)in_sizes; (void)n_in; (void)out_size;
    const float* x  = (const float*)d_in[0];
    const float* W0 = (const float*)d_in[1];
    const float* b0 = (const float*)d_in[2];
    const float* W1 = (const float*)d_in[3];
    const float* b1 = (const float*)d_in[4];
    const float* W2 = (const float*)d_in[5];
    const float* b2 = (const float*)d_in[6];
    const float* A  = (const float*)d_in[7];
    float* out = (float*)d_out;

    cudaFuncSetAttribute(k1_gemm0, cudaFuncAttributeMaxDynamicSharedMemorySize, K1_SMEMB);
    cudaFuncSetAttribute(k3_out,   cudaFuncAttributeMaxDynamicSharedMemorySize, K3_SMEMB);

    k1_gemm0<<<S_SPLIT, 128, K1_SMEMB>>>(x, W0);
    k2a_reduce<<<256, 256>>>(b0);
    k2b_mlp<<<N_, H_>>>(W1, b1, W2, b2);
    k3_out<<<N_ * (T_ / K3_T), 256, K3_SMEMB>>>(x, A, out);
}

// round 13
// speedup vs baseline: 1.0646x; 1.0646x over previous
#include <cuda_runtime.h>
#include <cuda_bf16.h>
#include <cstdint>

// Problem dims
#define N_  32
#define C_  64
#define T_  128
#define V_  25
#define F_  204800      // C*T*V
#define H_  256
#define E_  4

// Split-K config for GEMM0
#define S_SPLIT 512
#define FC      400     // F_/S_SPLIT
#define KT      16      // f-tile staged in smem
#define NTILES  (FC / KT)   // 25

// Scratch (static device globals — no allocation)
__device__ float g_partials[S_SPLIT * N_ * H_];   // 16.7 MB
__device__ float g_h0[N_ * H_];
__device__ float g_wgt[N_ * E_];

// ---------------- f32x2 helpers (sm_103a packed fp32 FMA) ----------------
static __device__ __forceinline__ unsigned long long pack2(float lo, float hi) {
    unsigned long long r;
    asm("mov.b64 %0, {%1, %2};" : "=l"(r) : "f"(lo), "f"(hi));
    return r;
}
static __device__ __forceinline__ void unpack2(unsigned long long p, float& lo, float& hi) {
    asm("mov.b64 {%0, %1}, %2;" : "=f"(lo), "=f"(hi) : "l"(p));
}
static __device__ __forceinline__ void ffma2(unsigned long long& acc,
                                             unsigned long long a,
                                             unsigned long long b) {
    asm("fma.rn.f32x2 %0, %1, %2, %0;" : "+l"(acc) : "l"(a), "l"(b));
}

static __device__ __forceinline__ void cp_async16(unsigned int smem_addr, const void* gptr) {
    asm volatile("cp.async.cg.shared.global [%0], [%1], 16;"
                 :: "r"(smem_addr), "l"(gptr));
}
static __device__ __forceinline__ void cp_commit() {
    asm volatile("cp.async.commit_group;");
}
static __device__ __forceinline__ void cp_wait_all() {
    asm volatile("cp.async.wait_group 0;");
}

// ---------------- Kernel 1: split-K GEMM0 (double-buffered, 256 thr) -------
// Grid: S_SPLIT blocks, 256 threads, occ 4 (32 warps/SM, 1 full wave).
// Thread tile: 8 n (4 f32x2 pairs) x 4 h.
__global__ __launch_bounds__(256, 4)
void k1_gemm0(const float* __restrict__ x, const float* __restrict__ W0) {
    __shared__ __align__(16) float w_sh[2][KT * H_];   // 2 x 16 KB
    __shared__ __align__(16) float x_sh[2][KT * 32];   // 2 x  2 KB

    const int tid = threadIdx.x;
    const int pg  = tid >> 6;            // 0..3  -> n-pair group (4 pairs = 8 n)
    const int hg  = tid & 63;            // 0..63 -> h group
    const int h0  = hg << 2;             // 4 h per thread
    const int fbase = blockIdx.x * FC;

    const int ln = (tid & 127) >> 2;     // 0..31 : n row for x staging
    const int lj = tid & 3;              // 0..3  : f quad

    unsigned long long acc[4][4];
#pragma unroll
    for (int i = 0; i < 4; i++)
#pragma unroll
        for (int j = 0; j < 4; j++) acc[i][j] = 0ull;

    // ---- prologue: stage tile 0 into buffer 0 ----
    {
        const int f0 = fbase;
        // W0 tile: KT*H_ floats = 1024 chunks of 16B; 4 per thread
#pragma unroll
        for (int k = 0; k < 4; k++) {
            const int cid = tid + 256 * k;         // 0..1023
            const int r   = cid >> 6;              // row 0..15
            const int c16 = cid & 63;              // 16B chunk in row
            unsigned int sa = (unsigned int)__cvta_generic_to_shared(
                                  &w_sh[0][r * H_ + c16 * 4]);
            cp_async16(sa, W0 + (size_t)(f0 + r) * H_ + c16 * 4);
        }
        cp_commit();
        if (tid < 128) {
            const float4 xv = *(const float4*)(x + (size_t)ln * F_ + f0 + lj * 4);
            x_sh[0][(lj * 4 + 0) * 32 + ln] = xv.x;
            x_sh[0][(lj * 4 + 1) * 32 + ln] = xv.y;
            x_sh[0][(lj * 4 + 2) * 32 + ln] = xv.z;
            x_sh[0][(lj * 4 + 3) * 32 + ln] = xv.w;
        }
        cp_wait_all();
    }
    __syncthreads();

    for (int t = 0; t < NTILES; t++) {
        const int buf  = t & 1;
        const int nbuf = buf ^ 1;
        const bool has_next = (t + 1 < NTILES);

        float4 xv;
        if (has_next) {
            const int f1 = fbase + (t + 1) * KT;
#pragma unroll
            for (int k = 0; k < 4; k++) {
                const int cid = tid + 256 * k;
                const int r   = cid >> 6;
                const int c16 = cid & 63;
                unsigned int sa = (unsigned int)__cvta_generic_to_shared(
                                      &w_sh[nbuf][r * H_ + c16 * 4]);
                cp_async16(sa, W0 + (size_t)(f1 + r) * H_ + c16 * 4);
            }
            cp_commit();
            if (tid < 128)
                xv = *(const float4*)(x + (size_t)ln * F_ + f1 + lj * 4);
        }

        // ---- compute tile t from smem ----
        const float* wb = &w_sh[buf][0];
        const float* xb = &x_sh[buf][0];
#pragma unroll
        for (int fl = 0; fl < KT; fl++) {
            const float4 w4 = *(const float4*)(wb + fl * H_ + h0);

            // 4 packed x pairs (broadcast within warp)
            const ulonglong2* xr = (const ulonglong2*)(xb + fl * 32 + pg * 8);
            const ulonglong2 q0 = xr[0], q1 = xr[1];
            const unsigned long long xp[4] = {q0.x, q0.y, q1.x, q1.y};

            {
                const unsigned long long w2 = pack2(w4.x, w4.x);
#pragma unroll
                for (int i = 0; i < 4; i++) ffma2(acc[i][0], xp[i], w2);
            }
            {
                const unsigned long long w2 = pack2(w4.y, w4.y);
#pragma unroll
                for (int i = 0; i < 4; i++) ffma2(acc[i][1], xp[i], w2);
            }
            {
                const unsigned long long w2 = pack2(w4.z, w4.z);
#pragma unroll
                for (int i = 0; i < 4; i++) ffma2(acc[i][2], xp[i], w2);
            }
            {
                const unsigned long long w2 = pack2(w4.w, w4.w);
#pragma unroll
                for (int i = 0; i < 4; i++) ffma2(acc[i][3], xp[i], w2);
            }
        }

        if (has_next) {
            if (tid < 128) {
                x_sh[nbuf][(lj * 4 + 0) * 32 + ln] = xv.x;
                x_sh[nbuf][(lj * 4 + 1) * 32 + ln] = xv.y;
                x_sh[nbuf][(lj * 4 + 2) * 32 + ln] = xv.z;
                x_sh[nbuf][(lj * 4 + 3) * 32 + ln] = xv.w;
            }
            cp_wait_all();
        }
        __syncthreads();
    }

    // Write deterministic partials
    float* outp = g_partials + (size_t)blockIdx.x * (N_ * H_);
#pragma unroll
    for (int i = 0; i < 4; i++) {
        const int n = (pg * 4 + i) * 2;
#pragma unroll
        for (int j = 0; j < 4; j++) {
            float lo, hi;
            unpack2(acc[i][j], lo, hi);
            outp[(n + 0) * H_ + h0 + j] = lo;
            outp[(n + 1) * H_ + h0 + j] = hi;
        }
    }
}

// ---------------- Kernel 2a: parallel split-K reduce + bias + ELU ----------
// Grid: 256 blocks = (32 n) x (8 h-groups); 256 threads = 32 h x 8 q-chunks.
__global__ __launch_bounds__(256)
void k2a_reduce(const float* __restrict__ b0) {
    __shared__ float red[8][33];

    const int n  = blockIdx.x >> 3;
    const int hq = blockIdx.x & 7;
    const int hl = threadIdx.x & 31;
    const int rg = threadIdx.x >> 5;     // 0..7
    const int h  = hq * 32 + hl;

    float s = 0.f;
    const float* p = g_partials + (size_t)n * H_ + h;
#pragma unroll 8
    for (int q = rg; q < S_SPLIT; q += 8)
        s += p[(size_t)q * (N_ * H_)];

    red[rg][hl] = s;
    __syncthreads();

    if (rg == 0) {
        float v = red[0][hl];
#pragma unroll
        for (int r = 1; r < 8; r++) v += red[r][hl];
        v += b0[h];
        v = (v > 0.f) ? v : expm1f(v);   // ELU
        g_h0[n * H_ + h] = v;
    }
}

// ---------------- Kernel 2b: MLP layers 2/3 + softmax -> g_wgt -------------
// Grid: 32 blocks (one per n), 256 threads (one per h).
__global__ __launch_bounds__(H_)
void k2b_mlp(const float* __restrict__ W1, const float* __restrict__ b1,
             const float* __restrict__ W2, const float* __restrict__ b2) {
    __shared__ float sh0[H_];
    __shared__ float sh1[H_];
    __shared__ float lg[E_];

    const int n = blockIdx.x;
    const int h = threadIdx.x;

    sh0[h] = g_h0[n * H_ + h];
    __syncthreads();

    float a = 0.f;
#pragma unroll 8
    for (int k = 0; k < H_; k++) a += sh0[k] * W1[k * H_ + h];
    a += b1[h];
    a = (a > 0.f) ? a : expm1f(a);
    sh1[h] = a;
    __syncthreads();

    if (h < E_) {
        float l = 0.f;
#pragma unroll 8
        for (int k = 0; k < H_; k++) l += sh1[k] * W2[k * E_ + h];
        lg[h] = l + b2[h];
    }
    __syncthreads();

    if (h == 0) {
        const float m = fmaxf(fmaxf(lg[0], lg[1]), fmaxf(lg[2], lg[3]));
        float e[E_];
        float den = 0.f;
#pragma unroll
        for (int ee = 0; ee < E_; ee++) { e[ee] = expf(lg[ee] - m); den += e[ee]; }
        const float inv = 1.f / den;
#pragma unroll
        for (int ee = 0; ee < E_; ee++) g_wgt[n * E_ + ee] = e[ee] * inv;
    }
}

// ---------------- Kernel 3: AS mix + batched graph conv (R6 version) -------
// Grid: 32 n x 32 t-quads = 1024 blocks, 256 threads.
// Thread (t = tid>>6, c = tid&63) computes out[n, c, t, 0..24].
#define K3_XPAD 26
#define K3_APAD 28
__global__ __launch_bounds__(256)
void k3_out(const float* __restrict__ x, const float* __restrict__ A,
            float* __restrict__ out) {
    __shared__ __align__(16) float x_sh[4 * C_ * K3_XPAD];   // 26.6 KB (reused for out)
    __shared__ __align__(16) float AS_sh[4 * V_ * K3_APAD];  // 11.2 KB
    __shared__ float wn[E_];

    const int tid = threadIdx.x;
    const int n   = blockIdx.x >> 5;
    const int tq  = blockIdx.x & 31;
    const int t0  = tq * 4;

    if (tid < E_) wn[tid] = g_wgt[n * E_ + tid];
    __syncthreads();

    // AS[t][v][w] = sum_e wn[e] * A[e][t0+t][v][w]
    for (int idx = tid; idx < 4 * V_ * V_; idx += 256) {
        const int tt = idx / (V_ * V_);
        const int r  = idx - tt * (V_ * V_);
        const int v  = r / V_;
        const int w  = r - v * V_;
        const float* Ab = A + (size_t)(t0 + tt) * (V_ * V_) + r;
        AS_sh[tt * (V_ * K3_APAD) + v * K3_APAD + w] =
              wn[0] * Ab[0]
            + wn[1] * Ab[1 * T_ * V_ * V_]
            + wn[2] * Ab[2 * T_ * V_ * V_]
            + wn[3] * Ab[3 * T_ * V_ * V_];
    }

    // Stage x[n, :, t0:t0+4, :] — 100 contiguous floats per c, float4 loads
    for (int q = tid; q < C_ * 25; q += 256) {           // 1600 float4
        const int c = q / 25;
        const int r = q - c * 25;
        const float4 xv = *(const float4*)(x + (size_t)n * F_ + c * (T_ * V_)
                                             + t0 * V_ + r * 4);
        const int m0 = r * 4;
#pragma unroll
        for (int s = 0; s < 4; s++) {
            const int m  = m0 + s;
            const int tt = m / 25;
            const int v  = m - tt * 25;
            const float val = (s == 0) ? xv.x : (s == 1) ? xv.y : (s == 2) ? xv.z : xv.w;
            x_sh[tt * (C_ * K3_XPAD) + c * K3_XPAD + v] = val;
        }
    }
    __syncthreads();

    const int tt = tid >> 6;             // warp-uniform (broadcast AS reads)
    const int c  = tid & 63;

    unsigned long long acc2[12];
#pragma unroll
    for (int j = 0; j < 12; j++) acc2[j] = 0ull;
    float acc1 = 0.f;

    const float* xrow = x_sh + tt * (C_ * K3_XPAD) + c * K3_XPAD;
    const float* asb  = AS_sh + tt * (V_ * K3_APAD);
#pragma unroll
    for (int v = 0; v < V_; v++) {
        const float xv = xrow[v];
        const unsigned long long xx = pack2(xv, xv);
        const unsigned long long* arow =
            (const unsigned long long*)(asb + v * K3_APAD);
#pragma unroll
        for (int j = 0; j < 12; j++) ffma2(acc2[j], xx, arow[j]);
        acc1 += xv * ((const float*)arow)[24];
    }

    __syncthreads();   // done reading x_sh — reuse as out staging

    float* osh = x_sh;                   // [c][100] layout
    float* orow = osh + c * 100 + tt * 25;
#pragma unroll
    for (int j = 0; j < 12; j++) {
        float lo, hi;
        unpack2(acc2[j], lo, hi);
        orow[2 * j + 0] = lo;
        orow[2 * j + 1] = hi;
    }
    orow[24] = acc1;
    __syncthreads();

    // Coalesced float4 copy-out: per c, 100 contiguous floats in gmem
    for (int q = tid; q < C_ * 25; q += 256) {
        const int c2 = q / 25;
        const int m  = q - c2 * 25;
        const float4 v4 = *(const float4*)(osh + c2 * 100 + m * 4);
        *(float4*)(out + (size_t)n * F_ + c2 * (T_ * V_) + t0 * V_ + m * 4) = v4;
    }
}

// ---------------- launch ----------------
extern "C" void kernel_launch(void* const* d_in, const int* in_sizes, int n_in,
                              void* d_out, int out_size) {
    (void)in_sizes; (void)n_in; (void)out_size;
    const float* x  = (const float*)d_in[0];
    const float* W0 = (const float*)d_in[1];
    const float* b0 = (const float*)d_in[2];
    const float* W1 = (const float*)d_in[3];
    const float* b1 = (const float*)d_in[4];
    const float* W2 = (const float*)d_in[5];
    const float* b2 = (const float*)d_in[6];
    const float* A  = (const float*)d_in[7];
    float* out = (float*)d_out;

    k1_gemm0<<<S_SPLIT, 256>>>(x, W0);
    k2a_reduce<<<256, 256>>>(b0);
    k2b_mlp<<<N_, H_>>>(W1, b1, W2, b2);
    k3_out<<<N_ * (T_ / 4), 256>>>(x, A, out);
}